// round 15
// baseline (speedup 1.0000x reference)
#include <cuda_runtime.h>
#include <cuda_fp16.h>
#include <math.h>
#include <stdint.h>

#define SEQ 2048
#define NB  16
#define DM  1024
#define DH  512

static constexpr size_t ROWS = (size_t)SEQ * NB;   // 32768

// ---- scratch (device globals; no allocation allowed) ----
__device__ __half g_xh[ROWS * DM];                   //  64 MB
__device__ __half g_qh[ROWS * DH];                   //  32 MB
__device__ __half g_kvh[ROWS * 2 * DH];              //  64 MB
__device__ __half g_attnh[(size_t)NB * SEQ * SEQ];   // 128 MB
__device__ __half g_vaTh[(size_t)NB * DH * SEQ];     //  32 MB
__device__ __half g_cqh[ROWS * DH];                  //  32 MB
__device__ __half g_Uh[ROWS * 3 * DM];               // 192 MB
__device__ __half g_W1Th[DH * DM];
__device__ __half g_W2Th[DM * DH];
__device__ __half g_W3Th[3 * DM * DH];
__device__ float  g_cst[NB * DM];                    // c-state handoff between recur segments

// ============================================================================
// helpers
// ============================================================================
__device__ __forceinline__ void mma_f16(float* c, const uint32_t* a, const uint32_t* b) {
    asm volatile(
        "mma.sync.aligned.m16n8k16.row.col.f32.f16.f16.f32 "
        "{%0,%1,%2,%3}, {%4,%5,%6,%7}, {%8,%9}, {%0,%1,%2,%3};"
        : "+f"(c[0]), "+f"(c[1]), "+f"(c[2]), "+f"(c[3])
        : "r"(a[0]), "r"(a[1]), "r"(a[2]), "r"(a[3]), "r"(b[0]), "r"(b[1]));
}

__device__ __forceinline__ void ldsm_x4(uint32_t& r0, uint32_t& r1, uint32_t& r2,
                                        uint32_t& r3, uint32_t addr) {
    asm volatile("ldmatrix.sync.aligned.m8n8.x4.shared.b16 {%0,%1,%2,%3}, [%4];"
                 : "=r"(r0), "=r"(r1), "=r"(r2), "=r"(r3) : "r"(addr));
}

__device__ __forceinline__ void cp16(uint32_t smem, const void* g) {
    asm volatile("cp.async.cg.shared.global [%0], [%1], 16;" :: "r"(smem), "l"(g));
}
__device__ __forceinline__ void cp_commit() { asm volatile("cp.async.commit_group;"); }
__device__ __forceinline__ void cp_wait1()  { asm volatile("cp.async.wait_group 1;"); }

// ============================================================================
// FP16 TN GEMM (fp32 accumulate): Ch = alpha * A @ B^T (+ Ad), batch = grid.z.
// Best-measured config: block tile 128x128x64, 128 threads, warps 2x2 (64x64),
// 3-stage cp.async, SW128 xor swizzle, b16 ldmatrix.x4, 2 CTAs/SM.
// ============================================================================
#define STAGES 3
#define BKH 64
#define TILE_BYTES (128 * BKH * 2)   // 16 KB per operand per stage

template<bool ADD>
__global__ __launch_bounds__(128, 2)
void gemm_h(const __half* __restrict__ A, const __half* __restrict__ B,
            __half* __restrict__ Ch, const __half* __restrict__ Ad,
            int K, int lda, int ldb, int ldch, int ldad, float alpha,
            long long sA, long long sB, long long sCh, long long sAd)
{
    A += (long long)blockIdx.z * sA;
    B += (long long)blockIdx.z * sB;
    Ch += (long long)blockIdx.z * sCh;
    if (ADD) Ad += (long long)blockIdx.z * sAd;

    extern __shared__ char smem[];
    const uint32_t smem_u32 = (uint32_t)__cvta_generic_to_shared(smem);
    const uint32_t a_base = smem_u32;
    const uint32_t b_base = smem_u32 + STAGES * TILE_BYTES;

    const int m0 = blockIdx.y * 128;
    const int n0 = blockIdx.x * 128;
    const int tid  = threadIdx.x;
    const int lane = tid & 31;
    const int warp = tid >> 5;
    const int wm = (warp >> 1) * 64;
    const int wn = (warp & 1) * 64;

    int lrow[8], lchk[8];
    uint32_t lsw[8];
    #pragma unroll
    for (int i = 0; i < 8; i++) {
        int id = i * 128 + tid;
        lrow[i] = id >> 3;
        lchk[i] = id & 7;
        lsw[i]  = (uint32_t)(lrow[i] * 128 + ((lchk[i] ^ (lrow[i] & 7)) << 4));
    }

    auto issue = [&](int kt, int buf) {
        const uint32_t ab = a_base + buf * TILE_BYTES;
        const uint32_t bb = b_base + buf * TILE_BYTES;
        const int k0 = kt * BKH;
        #pragma unroll
        for (int i = 0; i < 8; i++)
            cp16(ab + lsw[i], A + (long long)(m0 + lrow[i]) * lda + k0 + lchk[i] * 8);
        #pragma unroll
        for (int i = 0; i < 8; i++)
            cp16(bb + lsw[i], B + (long long)(n0 + lrow[i]) * ldb + k0 + lchk[i] * 8);
    };

    const int mi = lane >> 3;
    const int lr = lane & 7;
    const int row16 = (mi & 1) * 8 + lr;
    const int cadd  = mi >> 1;

    float acc[4][8][4];
    #pragma unroll
    for (int mt = 0; mt < 4; mt++)
        #pragma unroll
        for (int nt = 0; nt < 8; nt++)
            #pragma unroll
            for (int r = 0; r < 4; r++) acc[mt][nt][r] = 0.f;

    uint32_t af[2][4][4], bf[2][8][2];

    auto load_frags = [&](uint32_t ab, uint32_t bb, int s, int pb) {
        const int c = 2 * s + cadd;
        #pragma unroll
        for (int mt = 0; mt < 4; mt++) {
            int m = wm + mt * 16 + row16;
            ldsm_x4(af[pb][mt][0], af[pb][mt][1], af[pb][mt][2], af[pb][mt][3],
                    ab + m * 128 + ((c ^ (m & 7)) << 4));
        }
        #pragma unroll
        for (int np = 0; np < 4; np++) {
            int n = wn + np * 16 + row16;
            uint32_t r0, r1, r2, r3;
            ldsm_x4(r0, r1, r2, r3, bb + n * 128 + ((c ^ (n & 7)) << 4));
            bf[pb][2 * np][0]     = r0; bf[pb][2 * np][1]     = r2;
            bf[pb][2 * np + 1][0] = r1; bf[pb][2 * np + 1][1] = r3;
        }
    };

    const int KT = K / BKH;
    issue(0, 0); cp_commit();
    issue(1, 1); cp_commit();

    for (int kt = 0; kt < KT; kt++) {
        const int buf = kt % STAGES;
        cp_wait1();
        __syncthreads();

        if (kt + 2 < KT) issue(kt + 2, (kt + 2) % STAGES);
        cp_commit();

        const uint32_t ab = a_base + buf * TILE_BYTES;
        const uint32_t bb = b_base + buf * TILE_BYTES;

        load_frags(ab, bb, 0, 0);
        #pragma unroll
        for (int s = 0; s < 4; s++) {
            const int pb = s & 1;
            if (s < 3) load_frags(ab, bb, s + 1, pb ^ 1);
            #pragma unroll
            for (int mt = 0; mt < 4; mt++)
                #pragma unroll
                for (int nt = 0; nt < 8; nt++)
                    mma_f16(acc[mt][nt], af[pb][mt], bf[pb][nt]);
        }
    }

    const int g = lane >> 2;
    const int t = lane & 3;
    #pragma unroll
    for (int mt = 0; mt < 4; mt++) {
        int r0 = m0 + wm + mt * 16 + g;
        #pragma unroll
        for (int nt = 0; nt < 8; nt++) {
            int c0 = n0 + wn + nt * 8 + 2 * t;
            float* a4 = acc[mt][nt];
            float2 v0 = {alpha * a4[0], alpha * a4[1]};
            float2 v1 = {alpha * a4[2], alpha * a4[3]};
            if (ADD) {
                float2 d0 = __half22float2(*(const __half2*)(Ad + (long long)r0 * ldad + c0));
                float2 d1 = __half22float2(*(const __half2*)(Ad + (long long)(r0 + 8) * ldad + c0));
                v0.x += d0.x; v0.y += d0.y;
                v1.x += d1.x; v1.y += d1.y;
            }
            *(__half2*)(Ch + (long long)r0 * ldch + c0) = __floats2half2_rn(v0.x, v0.y);
            *(__half2*)(Ch + (long long)(r0 + 8) * ldch + c0) = __floats2half2_rn(v1.x, v1.y);
        }
    }
}

// ============================================================================
// Fused prep kernel: W1/W2/W3 transposes (f32->f16) + x conversion.
// ============================================================================
__device__ __forceinline__ void tr_tile(const float* __restrict__ in,
                                        __half* __restrict__ out,
                                        int ld_in, int ld_out, int rb, int cb)
{
    __shared__ float tile[32][33];
    const int tx = threadIdx.x & 31;
    const int ty = threadIdx.x >> 5;
    #pragma unroll
    for (int i = 0; i < 4; i++)
        tile[ty + i * 8][tx] = in[(long long)(rb + ty + i * 8) * ld_in + cb + tx];
    __syncthreads();
    #pragma unroll
    for (int i = 0; i < 4; i++)
        out[(long long)(cb + ty + i * 8) * ld_out + rb + tx] =
            __float2half(tile[tx][ty + i * 8]);
}

__global__ __launch_bounds__(256)
void prep_k(const float* __restrict__ x,  __half* __restrict__ xh,
            const float* __restrict__ W1, __half* __restrict__ W1T,
            const float* __restrict__ W2, __half* __restrict__ W2T,
            const float* __restrict__ W3, __half* __restrict__ W3T)
{
    const int bid = blockIdx.x;
    if (bid < 512) {
        int j = bid;
        tr_tile(W1, W1T, DH, DM, (j >> 4) * 32, (j & 15) * 32);
    } else if (bid < 1024) {
        int j = bid - 512;
        tr_tile(W2, W2T, DM, DH, (j >> 5) * 32, (j & 31) * 32);
    } else if (bid < 2560) {
        int j = bid - 1024;
        tr_tile(W3, W3T, 3 * DM, DH, (j / 96) * 32, (j % 96) * 32);
    } else {
        long long i = ((long long)(bid - 2560) * 256 + threadIdx.x) * 4;
        float4 v = *(const float4*)(x + i);
        *(__half2*)(xh + i)     = __floats2half2_rn(v.x, v.y);
        *(__half2*)(xh + i + 2) = __floats2half2_rn(v.z, v.w);
    }
}

// ============================================================================
// Tiled half->half transpose (batched) — for vaT
// ============================================================================
__global__ __launch_bounds__(256)
void transpose_h2h(const __half* __restrict__ in, __half* __restrict__ out,
                   long long ld_in, long long ld_out, long long sIn, long long sOut)
{
    in  += (long long)blockIdx.z * sIn;
    out += (long long)blockIdx.z * sOut;
    __shared__ float tile[32][33];
    const int rb = blockIdx.y * 32;
    const int cb = blockIdx.x * 32;
    const int tx = threadIdx.x & 31;
    const int ty = threadIdx.x >> 5;
    #pragma unroll
    for (int i = 0; i < 4; i++)
        tile[ty + i * 8][tx] = __half2float(in[(long long)(rb + ty + i * 8) * ld_in + cb + tx]);
    __syncthreads();
    #pragma unroll
    for (int i = 0; i < 4; i++)
        out[(long long)(cb + ty + i * 8) * ld_out + rb + tx] =
            __float2half(tile[tx][ty + i * 8]);
}

// ============================================================================
// In-place row softmax over 2048-wide fp16 rows — vectorized uint4.
// ============================================================================
__global__ __launch_bounds__(256)
void softmax2048h(__half* __restrict__ S)
{
    __half* row = S + (size_t)blockIdx.x * SEQ;
    const int tid = threadIdx.x;

    uint4 u = *(const uint4*)(row + tid * 8);
    const __half2* h2 = (const __half2*)&u;
    float vals[8];
    #pragma unroll
    for (int i = 0; i < 4; i++) {
        float2 f = __half22float2(h2[i]);
        vals[2 * i] = f.x; vals[2 * i + 1] = f.y;
    }

    float m = -1e30f;
    #pragma unroll
    for (int i = 0; i < 8; i++) m = fmaxf(m, vals[i]);

    __shared__ float rmax[8];
    __shared__ float rsum[8];

    #pragma unroll
    for (int o = 16; o; o >>= 1) m = fmaxf(m, __shfl_xor_sync(0xffffffffu, m, o));
    if ((tid & 31) == 0) rmax[tid >> 5] = m;
    __syncthreads();
    m = rmax[0];
    #pragma unroll
    for (int w = 1; w < 8; w++) m = fmaxf(m, rmax[w]);

    float s = 0.f;
    #pragma unroll
    for (int i = 0; i < 8; i++) {
        vals[i] = __expf(vals[i] - m);
        s += vals[i];
    }
    #pragma unroll
    for (int o = 16; o; o >>= 1) s += __shfl_xor_sync(0xffffffffu, s, o);
    if ((tid & 31) == 0) rsum[tid >> 5] = s;
    __syncthreads();
    s = rsum[0];
    #pragma unroll
    for (int w = 1; w < 8; w++) s += rsum[w];

    float inv = 1.f / s;
    uint4 o4;
    __half2* oh = (__half2*)&o4;
    #pragma unroll
    for (int i = 0; i < 4; i++)
        oh[i] = __floats2half2_rn(vals[2 * i] * inv, vals[2 * i + 1] * inv);
    *(uint4*)(row + tid * 8) = o4;
}

// ============================================================================
// Highway recurrence over l in [l0, l1); c-state chained via cst (bit-exact).
// ============================================================================
#define RDEPTH 16
#define RSTRIDE 320

__global__ __launch_bounds__(256)
void sru_recur4(const __half* __restrict__ U, const float* __restrict__ x,
                const float* __restrict__ v, const float* __restrict__ bias,
                float* __restrict__ h, float* __restrict__ cst, int l0, int l1)
{
    extern __shared__ char rbuf[];
    const int tid  = threadIdx.x;
    const int lane = tid & 31;
    const int warp = tid >> 5;

    const int ch  = blockIdx.x * 256 + tid;
    const int b   = ch / DM;
    const int d   = ch % DM;
    const int d0w = (blockIdx.x * 256 + warp * 32) % DM;

    const char* srcb = nullptr;
    long long strideB = 0;
    uint32_t doff = 0;
    if (lane < 12) {
        int arr = lane >> 2, chk = lane & 3;
        srcb = (const char*)(U + ((long long)l0 * NB + b) * 3 * DM
                               + (long long)arr * DM + d0w + chk * 8);
        strideB = (long long)NB * 3 * DM * 2;
        doff = (uint32_t)(arr * 64 + chk * 16);
    } else if (lane < 20) {
        int chk = lane - 12;
        srcb = (const char*)(x + ((long long)l0 * NB + b) * DM + d0w + chk * 4);
        strideB = (long long)NB * DM * 4;
        doff = (uint32_t)(192 + chk * 16);
    }

    const uint32_t wbase = (uint32_t)__cvta_generic_to_shared(rbuf) + warp * RDEPTH * RSTRIDE;

    #pragma unroll
    for (int s = 0; s < RDEPTH; s++) {
        if (lane < 20) { cp16(wbase + s * RSTRIDE + doff, srcb); srcb += strideB; }
        cp_commit();
    }

    const float vf = v[d],    vr = v[DM + d];
    const float bf = bias[d], br = bias[DM + d];
    float c = (l0 == 0) ? 0.f : cst[ch];
    float* hp = h + ((long long)l0 * NB + b) * DM + d;
    const long long hstride = (long long)NB * DM;
    const char* wsm = rbuf + warp * RDEPTH * RSTRIDE;

    for (int l = l0; l < l1; l++) {
        const int st = (l - l0) & (RDEPTH - 1);
        const char* sp = wsm + st * RSTRIDE;
        asm volatile("cp.async.wait_group %0;" :: "n"(RDEPTH - 1));
        __syncwarp();
        float xt   = __half2float(((const __half*)sp)[lane]);
        float fr   = __half2float(((const __half*)sp)[32 + lane]);
        float rr   = __half2float(((const __half*)sp)[64 + lane]);
        float xres = ((const float*)(sp + 192))[lane];
        __syncwarp();
        if (lane < 20 && l + RDEPTH < l1) {
            cp16(wbase + st * RSTRIDE + doff, srcb);
            srcb += strideB;
        }
        cp_commit();

        float f = 1.f / (1.f + __expf(-(fr + vf * c + bf)));
        float r = 1.f / (1.f + __expf(-(rr + vr * c + br)));
        c = f * c + (1.f - f) * xt;
        hp[0] = r * c + (1.f - r) * xres;
        hp += hstride;
    }

    if (l1 < SEQ) cst[ch] = c;
}

// ============================================================================
// Launch — EXACT R12 schedule (best measured: 1299us), with the single
// change of an uneven U/recur split at l=1280: recur1 (1280 steps, ~94us)
// hides fully under U part 2 (~116us); exposed tail shrinks 1024->768 steps.
// Same launch count and joins as R12. scores stays launch #4 for ncu.
// ============================================================================
extern "C" void kernel_launch(void* const* d_in, const int* in_sizes, int n_in,
                              void* d_out, int out_size)
{
    const float* x  = (const float*)d_in[0];
    const float* W1 = (const float*)d_in[1];
    const float* W2 = (const float*)d_in[2];
    const float* W3 = (const float*)d_in[3];
    const float* v  = (const float*)d_in[4];
    const float* bb = (const float*)d_in[5];
    float* h = (float*)d_out;

    __half *xh, *qh, *kvh, *attnh, *vaTh, *cqh, *Uh, *W1Th, *W2Th, *W3Th;
    float* cst;
    cudaGetSymbolAddress((void**)&xh,    g_xh);
    cudaGetSymbolAddress((void**)&qh,    g_qh);
    cudaGetSymbolAddress((void**)&kvh,   g_kvh);
    cudaGetSymbolAddress((void**)&attnh, g_attnh);
    cudaGetSymbolAddress((void**)&vaTh,  g_vaTh);
    cudaGetSymbolAddress((void**)&cqh,   g_cqh);
    cudaGetSymbolAddress((void**)&Uh,    g_Uh);
    cudaGetSymbolAddress((void**)&W1Th,  g_W1Th);
    cudaGetSymbolAddress((void**)&W2Th,  g_W2Th);
    cudaGetSymbolAddress((void**)&W3Th,  g_W3Th);
    cudaGetSymbolAddress((void**)&cst,   g_cst);

    const int smem_bytes = STAGES * 2 * TILE_BYTES;   // 96 KB
    const int rec_smem   = 8 * RDEPTH * RSTRIDE;      // 40 KB
    cudaFuncSetAttribute((const void*)gemm_h<false>, cudaFuncAttributeMaxDynamicSharedMemorySize, smem_bytes);
    cudaFuncSetAttribute((const void*)gemm_h<true>,  cudaFuncAttributeMaxDynamicSharedMemorySize, smem_bytes);
    cudaFuncSetAttribute((const void*)sru_recur4, cudaFuncAttributeMaxDynamicSharedMemorySize, rec_smem);

    cudaStream_t sB;
    cudaStreamCreateWithFlags(&sB, cudaStreamNonBlocking);
    cudaEvent_t eKv, eTr, eU1, eR1;
    cudaEventCreateWithFlags(&eKv, cudaEventDisableTiming);
    cudaEventCreateWithFlags(&eTr, cudaEventDisableTiming);
    cudaEventCreateWithFlags(&eU1, cudaEventDisableTiming);
    cudaEventCreateWithFlags(&eR1, cudaEventDisableTiming);

    const dim3 T(128);
    const float scale = 1.0f / sqrtf((float)DH);
    const int L1 = 1280;                   // uneven U/recur split point (l)
    const int M1 = L1 * NB;                // 20480 rows (multiple of 128)

    // 1: fused prep
    prep_k<<<2560 + (int)(ROWS * DM / 1024), 256>>>(x, xh, W1, W1Th, W2, W2Th, W3, W3Th);

    // 2: q = x @ W1 -> qh
    gemm_h<false><<<dim3(DH / 128, ROWS / 128, 1), T, smem_bytes>>>(
        xh, W1Th, qh, nullptr, DM, DM, DM, DH, 0, 1.f, 0, 0, 0, 0);

    // 3: kv = q @ W2 -> kvh
    gemm_h<false><<<dim3(2 * DH / 128, ROWS / 128, 1), T, smem_bytes>>>(
        qh, W2Th, kvh, nullptr, DH, DH, DH, 2 * DH, 0, 1.f, 0, 0, 0, 0);
    cudaEventRecord(eKv, 0);

    // 4 (PROFILED): scores[b] = scale * Q_b @ K_b^T -> attnh (all batches)
    gemm_h<false><<<dim3(SEQ / 128, SEQ / 128, NB), T, smem_bytes>>>(
        qh, kvh, attnh, nullptr, DH, NB * DH, NB * 2 * DH, SEQ, 0, scale,
        (long long)DH, (long long)(2 * DH), (long long)SEQ * SEQ, 0);

    // stream B: vaT transpose, overlapped with the scores GEMM
    cudaStreamWaitEvent(sB, eKv, 0);
    transpose_h2h<<<dim3(DH / 32, SEQ / 32, NB), 256, 0, sB>>>(
        kvh + DH, vaTh, (long long)NB * 2 * DH, SEQ,
        (long long)(2 * DH), (long long)DH * SEQ);
    cudaEventRecord(eTr, sB);

    // softmax in place (depends only on scores)
    softmax2048h<<<NB * SEQ, 256>>>(attnh);

    // ctx needs vaT -> join stream B
    cudaStreamWaitEvent(0, eTr, 0);
    gemm_h<true><<<dim3(DH / 128, SEQ / 128, NB), T, smem_bytes>>>(
        attnh, vaTh, cqh, qh, SEQ, SEQ, SEQ, NB * DH, NB * DH, 1.f,
        (long long)SEQ * SEQ, (long long)DH * SEQ, (long long)DH, (long long)DH);

    // U part 1: rows [0, M1)  (timesteps l < 1280)
    gemm_h<false><<<dim3(3 * DM / 128, M1 / 128, 1), T, smem_bytes>>>(
        cqh, W3Th, Uh, nullptr, DH, DH, DH, 3 * DM, 0, 1.f, 0, 0, 0, 0);
    cudaEventRecord(eU1, 0);

    // stream B: recurrence part 1 (l in [0,1280)) under U part 2
    cudaStreamWaitEvent(sB, eU1, 0);
    sru_recur4<<<(NB * DM) / 256, 256, rec_smem, sB>>>(
        Uh, x, v, bb, h, cst, 0, L1);
    cudaEventRecord(eR1, sB);

    // U part 2: rows [M1, 32768)
    gemm_h<false><<<dim3(3 * DM / 128, (int)(ROWS - M1) / 128, 1), T, smem_bytes>>>(
        cqh + (long long)M1 * DH, W3Th, Uh + (long long)M1 * 3 * DM, nullptr,
        DH, DH, DH, 3 * DM, 0, 1.f, 0, 0, 0, 0);

    // recurrence part 2 (l in [1280,2048)) after U part 2 + recur part 1
    cudaStreamWaitEvent(0, eR1, 0);
    sru_recur4<<<(NB * DM) / 256, 256, rec_smem>>>(
        Uh, x, v, bb, h, cst, L1, SEQ);
}

// round 16
// speedup vs baseline: 1.1816x; 1.1816x over previous
#include <cuda_runtime.h>
#include <cuda_fp16.h>
#include <math.h>
#include <stdint.h>

#define SEQ 2048
#define NB  16
#define DM  1024
#define DH  512

static constexpr size_t ROWS = (size_t)SEQ * NB;   // 32768

// ---- scratch (device globals; no allocation allowed) ----
__device__ __half g_xh[ROWS * DM];                   //  64 MB
__device__ __half g_qh[ROWS * DH];                   //  32 MB
__device__ __half g_kvh[ROWS * 2 * DH];              //  64 MB
__device__ __half g_attnh[(size_t)NB * SEQ * SEQ];   // 128 MB
__device__ __half g_vaTh[(size_t)NB * DH * SEQ];     //  32 MB
__device__ __half g_cqh[ROWS * DH];                  //  32 MB
__device__ __half g_Uh[ROWS * 3 * DM];               // 192 MB
__device__ __half g_W1Th[DH * DM];
__device__ __half g_W2Th[DM * DH];
__device__ __half g_W3Th[3 * DM * DH];
__device__ float  g_cst[NB * DM];                    // c-state handoff between recur halves

// ============================================================================
// helpers
// ============================================================================
__device__ __forceinline__ void mma_f16(float* c, const uint32_t* a, const uint32_t* b) {
    asm volatile(
        "mma.sync.aligned.m16n8k16.row.col.f32.f16.f16.f32 "
        "{%0,%1,%2,%3}, {%4,%5,%6,%7}, {%8,%9}, {%0,%1,%2,%3};"
        : "+f"(c[0]), "+f"(c[1]), "+f"(c[2]), "+f"(c[3])
        : "r"(a[0]), "r"(a[1]), "r"(a[2]), "r"(a[3]), "r"(b[0]), "r"(b[1]));
}

__device__ __forceinline__ void ldsm_x4(uint32_t& r0, uint32_t& r1, uint32_t& r2,
                                        uint32_t& r3, uint32_t addr) {
    asm volatile("ldmatrix.sync.aligned.m8n8.x4.shared.b16 {%0,%1,%2,%3}, [%4];"
                 : "=r"(r0), "=r"(r1), "=r"(r2), "=r"(r3) : "r"(addr));
}

__device__ __forceinline__ void cp16(uint32_t smem, const void* g) {
    asm volatile("cp.async.cg.shared.global [%0], [%1], 16;" :: "r"(smem), "l"(g));
}
__device__ __forceinline__ void cp_commit() { asm volatile("cp.async.commit_group;"); }
__device__ __forceinline__ void cp_wait1()  { asm volatile("cp.async.wait_group 1;"); }

// sigmoid via single MUFU.TANH: sigmoid(x) = 0.5*tanh(0.5x) + 0.5
__device__ __forceinline__ float sigmoid_tanh(float x) {
    float t;
    asm("tanh.approx.f32 %0, %1;" : "=f"(t) : "f"(0.5f * x));
    return fmaf(0.5f, t, 0.5f);
}

// ============================================================================
// FP16 TN GEMM (fp32 accumulate): Ch = alpha * A @ B^T (+ Ad), batch = grid.z.
// Best-measured config: block tile 128x128x64, 128 threads, warps 2x2 (64x64),
// 3-stage cp.async, SW128 xor swizzle, b16 ldmatrix.x4, 2 CTAs/SM.
// ============================================================================
#define STAGES 3
#define BKH 64
#define TILE_BYTES (128 * BKH * 2)   // 16 KB per operand per stage

template<bool ADD>
__global__ __launch_bounds__(128, 2)
void gemm_h(const __half* __restrict__ A, const __half* __restrict__ B,
            __half* __restrict__ Ch, const __half* __restrict__ Ad,
            int K, int lda, int ldb, int ldch, int ldad, float alpha,
            long long sA, long long sB, long long sCh, long long sAd)
{
    A += (long long)blockIdx.z * sA;
    B += (long long)blockIdx.z * sB;
    Ch += (long long)blockIdx.z * sCh;
    if (ADD) Ad += (long long)blockIdx.z * sAd;

    extern __shared__ char smem[];
    const uint32_t smem_u32 = (uint32_t)__cvta_generic_to_shared(smem);
    const uint32_t a_base = smem_u32;
    const uint32_t b_base = smem_u32 + STAGES * TILE_BYTES;

    const int m0 = blockIdx.y * 128;
    const int n0 = blockIdx.x * 128;
    const int tid  = threadIdx.x;
    const int lane = tid & 31;
    const int warp = tid >> 5;
    const int wm = (warp >> 1) * 64;
    const int wn = (warp & 1) * 64;

    int lrow[8], lchk[8];
    uint32_t lsw[8];
    #pragma unroll
    for (int i = 0; i < 8; i++) {
        int id = i * 128 + tid;
        lrow[i] = id >> 3;
        lchk[i] = id & 7;
        lsw[i]  = (uint32_t)(lrow[i] * 128 + ((lchk[i] ^ (lrow[i] & 7)) << 4));
    }

    auto issue = [&](int kt, int buf) {
        const uint32_t ab = a_base + buf * TILE_BYTES;
        const uint32_t bb = b_base + buf * TILE_BYTES;
        const int k0 = kt * BKH;
        #pragma unroll
        for (int i = 0; i < 8; i++)
            cp16(ab + lsw[i], A + (long long)(m0 + lrow[i]) * lda + k0 + lchk[i] * 8);
        #pragma unroll
        for (int i = 0; i < 8; i++)
            cp16(bb + lsw[i], B + (long long)(n0 + lrow[i]) * ldb + k0 + lchk[i] * 8);
    };

    const int mi = lane >> 3;
    const int lr = lane & 7;
    const int row16 = (mi & 1) * 8 + lr;
    const int cadd  = mi >> 1;

    float acc[4][8][4];
    #pragma unroll
    for (int mt = 0; mt < 4; mt++)
        #pragma unroll
        for (int nt = 0; nt < 8; nt++)
            #pragma unroll
            for (int r = 0; r < 4; r++) acc[mt][nt][r] = 0.f;

    uint32_t af[2][4][4], bf[2][8][2];

    auto load_frags = [&](uint32_t ab, uint32_t bb, int s, int pb) {
        const int c = 2 * s + cadd;
        #pragma unroll
        for (int mt = 0; mt < 4; mt++) {
            int m = wm + mt * 16 + row16;
            ldsm_x4(af[pb][mt][0], af[pb][mt][1], af[pb][mt][2], af[pb][mt][3],
                    ab + m * 128 + ((c ^ (m & 7)) << 4));
        }
        #pragma unroll
        for (int np = 0; np < 4; np++) {
            int n = wn + np * 16 + row16;
            uint32_t r0, r1, r2, r3;
            ldsm_x4(r0, r1, r2, r3, bb + n * 128 + ((c ^ (n & 7)) << 4));
            bf[pb][2 * np][0]     = r0; bf[pb][2 * np][1]     = r2;
            bf[pb][2 * np + 1][0] = r1; bf[pb][2 * np + 1][1] = r3;
        }
    };

    const int KT = K / BKH;
    issue(0, 0); cp_commit();
    issue(1, 1); cp_commit();

    for (int kt = 0; kt < KT; kt++) {
        const int buf = kt % STAGES;
        cp_wait1();
        __syncthreads();

        if (kt + 2 < KT) issue(kt + 2, (kt + 2) % STAGES);
        cp_commit();

        const uint32_t ab = a_base + buf * TILE_BYTES;
        const uint32_t bb = b_base + buf * TILE_BYTES;

        load_frags(ab, bb, 0, 0);
        #pragma unroll
        for (int s = 0; s < 4; s++) {
            const int pb = s & 1;
            if (s < 3) load_frags(ab, bb, s + 1, pb ^ 1);
            #pragma unroll
            for (int mt = 0; mt < 4; mt++)
                #pragma unroll
                for (int nt = 0; nt < 8; nt++)
                    mma_f16(acc[mt][nt], af[pb][mt], bf[pb][nt]);
        }
    }

    const int g = lane >> 2;
    const int t = lane & 3;
    #pragma unroll
    for (int mt = 0; mt < 4; mt++) {
        int r0 = m0 + wm + mt * 16 + g;
        #pragma unroll
        for (int nt = 0; nt < 8; nt++) {
            int c0 = n0 + wn + nt * 8 + 2 * t;
            float* a4 = acc[mt][nt];
            float2 v0 = {alpha * a4[0], alpha * a4[1]};
            float2 v1 = {alpha * a4[2], alpha * a4[3]};
            if (ADD) {
                float2 d0 = __half22float2(*(const __half2*)(Ad + (long long)r0 * ldad + c0));
                float2 d1 = __half22float2(*(const __half2*)(Ad + (long long)(r0 + 8) * ldad + c0));
                v0.x += d0.x; v0.y += d0.y;
                v1.x += d1.x; v1.y += d1.y;
            }
            *(__half2*)(Ch + (long long)r0 * ldch + c0) = __floats2half2_rn(v0.x, v0.y);
            *(__half2*)(Ch + (long long)(r0 + 8) * ldch + c0) = __floats2half2_rn(v1.x, v1.y);
        }
    }
}

// ============================================================================
// Fused prep kernel: W1/W2/W3 transposes (f32->f16) + x conversion.
// ============================================================================
__device__ __forceinline__ void tr_tile(const float* __restrict__ in,
                                        __half* __restrict__ out,
                                        int ld_in, int ld_out, int rb, int cb)
{
    __shared__ float tile[32][33];
    const int tx = threadIdx.x & 31;
    const int ty = threadIdx.x >> 5;
    #pragma unroll
    for (int i = 0; i < 4; i++)
        tile[ty + i * 8][tx] = in[(long long)(rb + ty + i * 8) * ld_in + cb + tx];
    __syncthreads();
    #pragma unroll
    for (int i = 0; i < 4; i++)
        out[(long long)(cb + ty + i * 8) * ld_out + rb + tx] =
            __float2half(tile[tx][ty + i * 8]);
}

__global__ __launch_bounds__(256)
void prep_k(const float* __restrict__ x,  __half* __restrict__ xh,
            const float* __restrict__ W1, __half* __restrict__ W1T,
            const float* __restrict__ W2, __half* __restrict__ W2T,
            const float* __restrict__ W3, __half* __restrict__ W3T)
{
    const int bid = blockIdx.x;
    if (bid < 512) {
        int j = bid;
        tr_tile(W1, W1T, DH, DM, (j >> 4) * 32, (j & 15) * 32);
    } else if (bid < 1024) {
        int j = bid - 512;
        tr_tile(W2, W2T, DM, DH, (j >> 5) * 32, (j & 31) * 32);
    } else if (bid < 2560) {
        int j = bid - 1024;
        tr_tile(W3, W3T, 3 * DM, DH, (j / 96) * 32, (j % 96) * 32);
    } else {
        long long i = ((long long)(bid - 2560) * 256 + threadIdx.x) * 4;
        float4 v = *(const float4*)(x + i);
        *(__half2*)(xh + i)     = __floats2half2_rn(v.x, v.y);
        *(__half2*)(xh + i + 2) = __floats2half2_rn(v.z, v.w);
    }
}

// ============================================================================
// Tiled half->half transpose (batched) — for vaT
// ============================================================================
__global__ __launch_bounds__(256)
void transpose_h2h(const __half* __restrict__ in, __half* __restrict__ out,
                   long long ld_in, long long ld_out, long long sIn, long long sOut)
{
    in  += (long long)blockIdx.z * sIn;
    out += (long long)blockIdx.z * sOut;
    __shared__ float tile[32][33];
    const int rb = blockIdx.y * 32;
    const int cb = blockIdx.x * 32;
    const int tx = threadIdx.x & 31;
    const int ty = threadIdx.x >> 5;
    #pragma unroll
    for (int i = 0; i < 4; i++)
        tile[ty + i * 8][tx] = __half2float(in[(long long)(rb + ty + i * 8) * ld_in + cb + tx]);
    __syncthreads();
    #pragma unroll
    for (int i = 0; i < 4; i++)
        out[(long long)(cb + ty + i * 8) * ld_out + rb + tx] =
            __float2half(tile[tx][ty + i * 8]);
}

// ============================================================================
// In-place row softmax over 2048-wide fp16 rows — vectorized uint4.
// ============================================================================
__global__ __launch_bounds__(256)
void softmax2048h(__half* __restrict__ S)
{
    __half* row = S + (size_t)blockIdx.x * SEQ;
    const int tid = threadIdx.x;

    uint4 u = *(const uint4*)(row + tid * 8);
    const __half2* h2 = (const __half2*)&u;
    float vals[8];
    #pragma unroll
    for (int i = 0; i < 4; i++) {
        float2 f = __half22float2(h2[i]);
        vals[2 * i] = f.x; vals[2 * i + 1] = f.y;
    }

    float m = -1e30f;
    #pragma unroll
    for (int i = 0; i < 8; i++) m = fmaxf(m, vals[i]);

    __shared__ float rmax[8];
    __shared__ float rsum[8];

    #pragma unroll
    for (int o = 16; o; o >>= 1) m = fmaxf(m, __shfl_xor_sync(0xffffffffu, m, o));
    if ((tid & 31) == 0) rmax[tid >> 5] = m;
    __syncthreads();
    m = rmax[0];
    #pragma unroll
    for (int w = 1; w < 8; w++) m = fmaxf(m, rmax[w]);

    float s = 0.f;
    #pragma unroll
    for (int i = 0; i < 8; i++) {
        vals[i] = __expf(vals[i] - m);
        s += vals[i];
    }
    #pragma unroll
    for (int o = 16; o; o >>= 1) s += __shfl_xor_sync(0xffffffffu, s, o);
    if ((tid & 31) == 0) rsum[tid >> 5] = s;
    __syncthreads();
    s = rsum[0];
    #pragma unroll
    for (int w = 1; w < 8; w++) s += rsum[w];

    float inv = 1.f / s;
    uint4 o4;
    __half2* oh = (__half2*)&o4;
    #pragma unroll
    for (int i = 0; i < 4; i++)
        oh[i] = __floats2half2_rn(vals[2 * i] * inv, vals[2 * i + 1] * inv);
    *(uint4*)(row + tid * 8) = o4;
}

// ============================================================================
// Highway recurrence over l in [l0, l1); c-state chained via cst.
// Gates computed with MUFU.TANH sigmoid (1 MUFU vs EX2+RCP chain):
// carried-dependency chain ~28 cyc/step vs ~48 before.
// ============================================================================
#define RDEPTH 16
#define RSTRIDE 320

__global__ __launch_bounds__(256)
void sru_recur5(const __half* __restrict__ U, const float* __restrict__ x,
                const float* __restrict__ v, const float* __restrict__ bias,
                float* __restrict__ h, float* __restrict__ cst, int l0, int l1)
{
    extern __shared__ char rbuf[];
    const int tid  = threadIdx.x;
    const int lane = tid & 31;
    const int warp = tid >> 5;

    const int ch  = blockIdx.x * 256 + tid;
    const int b   = ch / DM;
    const int d   = ch % DM;
    const int d0w = (blockIdx.x * 256 + warp * 32) % DM;

    const char* srcb = nullptr;
    long long strideB = 0;
    uint32_t doff = 0;
    if (lane < 12) {
        int arr = lane >> 2, chk = lane & 3;
        srcb = (const char*)(U + ((long long)l0 * NB + b) * 3 * DM
                               + (long long)arr * DM + d0w + chk * 8);
        strideB = (long long)NB * 3 * DM * 2;
        doff = (uint32_t)(arr * 64 + chk * 16);
    } else if (lane < 20) {
        int chk = lane - 12;
        srcb = (const char*)(x + ((long long)l0 * NB + b) * DM + d0w + chk * 4);
        strideB = (long long)NB * DM * 4;
        doff = (uint32_t)(192 + chk * 16);
    }

    const uint32_t wbase = (uint32_t)__cvta_generic_to_shared(rbuf) + warp * RDEPTH * RSTRIDE;

    #pragma unroll
    for (int s = 0; s < RDEPTH; s++) {
        if (lane < 20) { cp16(wbase + s * RSTRIDE + doff, srcb); srcb += strideB; }
        cp_commit();
    }

    const float vf = v[d],    vr = v[DM + d];
    const float bf = bias[d], br = bias[DM + d];
    float c = (l0 == 0) ? 0.f : cst[ch];
    float* hp = h + ((long long)l0 * NB + b) * DM + d;
    const long long hstride = (long long)NB * DM;
    const char* wsm = rbuf + warp * RDEPTH * RSTRIDE;

    for (int l = l0; l < l1; l++) {
        const int st = (l - l0) & (RDEPTH - 1);
        const char* sp = wsm + st * RSTRIDE;
        asm volatile("cp.async.wait_group %0;" :: "n"(RDEPTH - 1));
        __syncwarp();
        float xt   = __half2float(((const __half*)sp)[lane]);
        float fr   = __half2float(((const __half*)sp)[32 + lane]);
        float rr   = __half2float(((const __half*)sp)[64 + lane]);
        float xres = ((const float*)(sp + 192))[lane];
        __syncwarp();
        if (lane < 20 && l + RDEPTH < l1) {
            cp16(wbase + st * RSTRIDE + doff, srcb);
            srcb += strideB;
        }
        cp_commit();

        float f = sigmoid_tanh(fr + vf * c + bf);
        float r = sigmoid_tanh(rr + vr * c + br);
        c = f * c + (1.f - f) * xt;
        hp[0] = r * c + (1.f - r) * xres;
        hp += hstride;
    }

    if (l1 < SEQ) cst[ch] = c;
}

// ============================================================================
// Launch — EXACT R12 schedule (best measured: 1299us, even U/recur split at
// l=1024), recurrence kernel upgraded to MUFU.TANH sigmoid.
// scores stays launch #4 (ncu capture window).
// ============================================================================
extern "C" void kernel_launch(void* const* d_in, const int* in_sizes, int n_in,
                              void* d_out, int out_size)
{
    const float* x  = (const float*)d_in[0];
    const float* W1 = (const float*)d_in[1];
    const float* W2 = (const float*)d_in[2];
    const float* W3 = (const float*)d_in[3];
    const float* v  = (const float*)d_in[4];
    const float* bb = (const float*)d_in[5];
    float* h = (float*)d_out;

    __half *xh, *qh, *kvh, *attnh, *vaTh, *cqh, *Uh, *W1Th, *W2Th, *W3Th;
    float* cst;
    cudaGetSymbolAddress((void**)&xh,    g_xh);
    cudaGetSymbolAddress((void**)&qh,    g_qh);
    cudaGetSymbolAddress((void**)&kvh,   g_kvh);
    cudaGetSymbolAddress((void**)&attnh, g_attnh);
    cudaGetSymbolAddress((void**)&vaTh,  g_vaTh);
    cudaGetSymbolAddress((void**)&cqh,   g_cqh);
    cudaGetSymbolAddress((void**)&Uh,    g_Uh);
    cudaGetSymbolAddress((void**)&W1Th,  g_W1Th);
    cudaGetSymbolAddress((void**)&W2Th,  g_W2Th);
    cudaGetSymbolAddress((void**)&W3Th,  g_W3Th);
    cudaGetSymbolAddress((void**)&cst,   g_cst);

    const int smem_bytes = STAGES * 2 * TILE_BYTES;   // 96 KB
    const int rec_smem   = 8 * RDEPTH * RSTRIDE;      // 40 KB
    cudaFuncSetAttribute((const void*)gemm_h<false>, cudaFuncAttributeMaxDynamicSharedMemorySize, smem_bytes);
    cudaFuncSetAttribute((const void*)gemm_h<true>,  cudaFuncAttributeMaxDynamicSharedMemorySize, smem_bytes);
    cudaFuncSetAttribute((const void*)sru_recur5, cudaFuncAttributeMaxDynamicSharedMemorySize, rec_smem);

    cudaStream_t sB;
    cudaStreamCreateWithFlags(&sB, cudaStreamNonBlocking);
    cudaEvent_t eKv, eTr, eU1, eR1;
    cudaEventCreateWithFlags(&eKv, cudaEventDisableTiming);
    cudaEventCreateWithFlags(&eTr, cudaEventDisableTiming);
    cudaEventCreateWithFlags(&eU1, cudaEventDisableTiming);
    cudaEventCreateWithFlags(&eR1, cudaEventDisableTiming);

    const dim3 T(128);
    const float scale = 1.0f / sqrtf((float)DH);
    const int HM = (int)(ROWS / 2);   // 16384 rows = l < 1024 (even split, as in R12)

    // 1: fused prep
    prep_k<<<2560 + (int)(ROWS * DM / 1024), 256>>>(x, xh, W1, W1Th, W2, W2Th, W3, W3Th);

    // 2: q = x @ W1 -> qh
    gemm_h<false><<<dim3(DH / 128, ROWS / 128, 1), T, smem_bytes>>>(
        xh, W1Th, qh, nullptr, DM, DM, DM, DH, 0, 1.f, 0, 0, 0, 0);

    // 3: kv = q @ W2 -> kvh
    gemm_h<false><<<dim3(2 * DH / 128, ROWS / 128, 1), T, smem_bytes>>>(
        qh, W2Th, kvh, nullptr, DH, DH, DH, 2 * DH, 0, 1.f, 0, 0, 0, 0);
    cudaEventRecord(eKv, 0);

    // 4 (PROFILED): scores[b] = scale * Q_b @ K_b^T -> attnh
    gemm_h<false><<<dim3(SEQ / 128, SEQ / 128, NB), T, smem_bytes>>>(
        qh, kvh, attnh, nullptr, DH, NB * DH, NB * 2 * DH, SEQ, 0, scale,
        (long long)DH, (long long)(2 * DH), (long long)SEQ * SEQ, 0);

    // stream B: vaT transpose, overlapped with the scores GEMM
    cudaStreamWaitEvent(sB, eKv, 0);
    transpose_h2h<<<dim3(DH / 32, SEQ / 32, NB), 256, 0, sB>>>(
        kvh + DH, vaTh, (long long)NB * 2 * DH, SEQ,
        (long long)(2 * DH), (long long)DH * SEQ);
    cudaEventRecord(eTr, sB);

    // softmax in place
    softmax2048h<<<NB * SEQ, 256>>>(attnh);

    // ctx needs vaT -> join stream B
    cudaStreamWaitEvent(0, eTr, 0);
    gemm_h<true><<<dim3(DH / 128, SEQ / 128, NB), T, smem_bytes>>>(
        attnh, vaTh, cqh, qh, SEQ, SEQ, SEQ, NB * DH, NB * DH, 1.f,
        (long long)SEQ * SEQ, (long long)DH * SEQ, (long long)DH, (long long)DH);

    // U part 1: rows [0, 16384)  (timesteps l < 1024)
    gemm_h<false><<<dim3(3 * DM / 128, HM / 128, 1), T, smem_bytes>>>(
        cqh, W3Th, Uh, nullptr, DH, DH, DH, 3 * DM, 0, 1.f, 0, 0, 0, 0);
    cudaEventRecord(eU1, 0);

    // stream B: recurrence part 1 (l in [0,1024)) under U part 2
    cudaStreamWaitEvent(sB, eU1, 0);
    sru_recur5<<<(NB * DM) / 256, 256, rec_smem, sB>>>(
        Uh, x, v, bb, h, cst, 0, SEQ / 2);
    cudaEventRecord(eR1, sB);

    // U part 2: rows [16384, 32768)
    gemm_h<false><<<dim3(3 * DM / 128, HM / 128, 1), T, smem_bytes>>>(
        cqh + (long long)HM * DH, W3Th, Uh + (long long)HM * 3 * DM, nullptr,
        DH, DH, DH, 3 * DM, 0, 1.f, 0, 0, 0, 0);

    // recurrence part 2 (l in [1024,2048)) after U part 2 + recur part 1
    cudaStreamWaitEvent(0, eR1, 0);
    sru_recur5<<<(NB * DM) / 256, 256, rec_smem>>>(
        Uh, x, v, bb, h, cst, SEQ / 2, SEQ);
}